// round 6
// baseline (speedup 1.0000x reference)
#include <cuda_runtime.h>
#include <cstdint>

// VolumeRenderer: per-ray exclusive-cumprod transmittance * alpha, dot with rgb.
// alpha: [R,128,1] f32, rgbs: [R,128,3] f32 -> out [R,3] f32.
//
// R1 body (1 warp per ray, fully coalesced float4 loads, warp scan + butterfly)
// inside a persistent grid-stride loop: one wave of 1216 CTAs instead of
// 16384 CTAs / 13.5 waves. No manual pipelining (keeps regs ~30, occ ~64 w/SM).

#define EPS 1e-10f

__global__ __launch_bounds__(256) void volume_render_persist(
    const float* __restrict__ alpha,
    const float* __restrict__ rgbs,
    float* __restrict__ out,
    int R)
{
    const int lane = threadIdx.x & 31;
    const int gwarp = (blockIdx.x * blockDim.x + threadIdx.x) >> 5;
    const int nwarps = (gridDim.x * blockDim.x) >> 5;

    #pragma unroll 1
    for (int ray = gwarp; ray < R; ray += nwarps) {
        const size_t rb = (size_t)ray;

        // ---- coalesced loads: alpha 512B/warp, rgb 1536B/warp ----
        const float4 a4 = *(reinterpret_cast<const float4*>(alpha + rb * 128) + lane);
        const float4* rg = reinterpret_cast<const float4*>(rgbs + rb * 384) + lane * 3;
        const float4 r0 = rg[0];
        const float4 r1 = rg[1];
        const float4 r2 = rg[2];

        const float t0 = 1.0f - a4.x + EPS;
        const float t1 = 1.0f - a4.y + EPS;
        const float t2 = 1.0f - a4.z + EPS;
        const float t3 = 1.0f - a4.w + EPS;

        // inclusive warp scan (product) of per-lane 4-factor products
        float incl = (t0 * t1) * (t2 * t3);
        #pragma unroll
        for (int off = 1; off < 32; off <<= 1) {
            const float v = __shfl_up_sync(0xffffffffu, incl, off);
            if (lane >= off) incl *= v;
        }
        float excl = __shfl_up_sync(0xffffffffu, incl, 1);
        if (lane == 0) excl = 1.0f;

        // weighted accumulation over this lane's 4 samples
        float acc0 = 0.f, acc1 = 0.f, acc2 = 0.f;
        {
            float tr = excl, w;
            w = tr * a4.x; acc0 = fmaf(w, r0.x, acc0); acc1 = fmaf(w, r0.y, acc1); acc2 = fmaf(w, r0.z, acc2); tr *= t0;
            w = tr * a4.y; acc0 = fmaf(w, r0.w, acc0); acc1 = fmaf(w, r1.x, acc1); acc2 = fmaf(w, r1.y, acc2); tr *= t1;
            w = tr * a4.z; acc0 = fmaf(w, r1.z, acc0); acc1 = fmaf(w, r1.w, acc1); acc2 = fmaf(w, r2.x, acc2); tr *= t2;
            w = tr * a4.w; acc0 = fmaf(w, r2.y, acc0); acc1 = fmaf(w, r2.z, acc1); acc2 = fmaf(w, r2.w, acc2);
        }

        // butterfly reduce 3 channels across the warp
        #pragma unroll
        for (int off = 16; off > 0; off >>= 1) {
            acc0 += __shfl_xor_sync(0xffffffffu, acc0, off);
            acc1 += __shfl_xor_sync(0xffffffffu, acc1, off);
            acc2 += __shfl_xor_sync(0xffffffffu, acc2, off);
        }

        if (lane < 3) {
            const float v = (lane == 0) ? acc0 : ((lane == 1) ? acc1 : acc2);
            out[rb * 3 + lane] = v;
        }
    }
}

extern "C" void kernel_launch(void* const* d_in, const int* in_sizes, int n_in,
                              void* d_out, int out_size)
{
    const float* alpha = (const float*)d_in[0];   // [R,128,1]
    const float* rgbs  = (const float*)d_in[1];   // [R,128,3]
    float* out = (float*)d_out;                   // [R,3]

    const int R = in_sizes[0] / 128;

    const int threads = 256;          // 8 warps/block
    int blocks = 152 * 8;             // one full-occupancy wave (64 warps/SM)
    const int maxBlocks = (R + 7) / 8;
    if (blocks > maxBlocks) blocks = maxBlocks;

    volume_render_persist<<<blocks, threads>>>(alpha, rgbs, out, R);
}

// round 7
// speedup vs baseline: 1.1391x; 1.1391x over previous
#include <cuda_runtime.h>
#include <cstdint>

// VolumeRenderer: per-ray exclusive-cumprod transmittance * alpha, dot with rgb.
// alpha: [R, 128, 1] f32, rgbs: [R, 128, 3] f32 -> out [R, 3] f32.
// One warp per ray; lane l handles samples [4l, 4l+4).
// R1 body + ld.global.nc.L2::256B (promote DRAM fetches to 256B granules).

#define EPS 1e-10f

__device__ __forceinline__ float4 ldg256(const float4* p) {
    float4 v;
    asm("ld.global.nc.L2::256B.v4.f32 {%0,%1,%2,%3}, [%4];"
        : "=f"(v.x), "=f"(v.y), "=f"(v.z), "=f"(v.w)
        : "l"(p));
    return v;
}

__global__ __launch_bounds__(256) void volume_render_kernel(
    const float* __restrict__ alpha,
    const float* __restrict__ rgbs,
    float* __restrict__ out,
    int R)
{
    const int warp_id = (blockIdx.x * blockDim.x + threadIdx.x) >> 5;
    const int lane = threadIdx.x & 31;
    if (warp_id >= R) return;

    const size_t ray = (size_t)warp_id;

    // ---- load 4 alphas (contiguous per warp: 128 floats) ----
    const float4 a4 = ldg256(reinterpret_cast<const float4*>(alpha + ray * 128) + lane);

    const float t0 = 1.0f - a4.x + EPS;
    const float t1 = 1.0f - a4.y + EPS;
    const float t2 = 1.0f - a4.z + EPS;
    const float t3 = 1.0f - a4.w + EPS;

    // per-lane product of the 4 transmittance factors
    const float local = ((t0 * t1) * (t2 * t3));

    // inclusive warp scan (product) over lanes
    float incl = local;
    #pragma unroll
    for (int off = 1; off < 32; off <<= 1) {
        float v = __shfl_up_sync(0xffffffffu, incl, off);
        if (lane >= off) incl *= v;
    }
    // exclusive prefix for this lane
    float excl = __shfl_up_sync(0xffffffffu, incl, 1);
    if (lane == 0) excl = 1.0f;

    // ---- load 12 rgb floats (3 x float4, 16B-aligned) ----
    const float4* rg = reinterpret_cast<const float4*>(rgbs + ray * 384) + lane * 3;
    const float4 r0 = ldg256(rg + 0);
    const float4 r1 = ldg256(rg + 1);
    const float4 r2 = ldg256(rg + 2);

    // ---- weighted accumulation over this lane's 4 samples ----
    float acc0 = 0.0f, acc1 = 0.0f, acc2 = 0.0f;
    float tr = excl;

    float w = tr * a4.x;
    acc0 = fmaf(w, r0.x, acc0); acc1 = fmaf(w, r0.y, acc1); acc2 = fmaf(w, r0.z, acc2);
    tr *= t0;

    w = tr * a4.y;
    acc0 = fmaf(w, r0.w, acc0); acc1 = fmaf(w, r1.x, acc1); acc2 = fmaf(w, r1.y, acc2);
    tr *= t1;

    w = tr * a4.z;
    acc0 = fmaf(w, r1.z, acc0); acc1 = fmaf(w, r1.w, acc1); acc2 = fmaf(w, r2.x, acc2);
    tr *= t2;

    w = tr * a4.w;
    acc0 = fmaf(w, r2.y, acc0); acc1 = fmaf(w, r2.z, acc1); acc2 = fmaf(w, r2.w, acc2);

    // ---- butterfly reduce the 3 channels across the warp ----
    #pragma unroll
    for (int off = 16; off > 0; off >>= 1) {
        acc0 += __shfl_xor_sync(0xffffffffu, acc0, off);
        acc1 += __shfl_xor_sync(0xffffffffu, acc1, off);
        acc2 += __shfl_xor_sync(0xffffffffu, acc2, off);
    }

    // lanes 0..2 write one channel each -> contiguous 12B store
    if (lane < 3) {
        float v = (lane == 0) ? acc0 : ((lane == 1) ? acc1 : acc2);
        out[ray * 3 + lane] = v;
    }
}

extern "C" void kernel_launch(void* const* d_in, const int* in_sizes, int n_in,
                              void* d_out, int out_size)
{
    const float* alpha = (const float*)d_in[0];   // [R,128,1]
    const float* rgbs  = (const float*)d_in[1];   // [R,128,3]
    float* out = (float*)d_out;                   // [R,3]

    const int R = in_sizes[0] / 128;

    const int threads = 256;              // 8 warps/block = 8 rays/block
    const int rays_per_block = threads / 32;
    const int blocks = (R + rays_per_block - 1) / rays_per_block;

    volume_render_kernel<<<blocks, threads>>>(alpha, rgbs, out, R);
}